// round 2
// baseline (speedup 1.0000x reference)
#include <cuda_runtime.h>
#include <cuda_fp16.h>
#include <cstdint>

// ============================================================
// ShiftConv on sm_103 (non-'a' ptx target): HMMA mma.sync fp16 GEMM.
// out[b,o,h,w] = bias[o] + sum_s sum_c W[o, s*192+c] * x[b,c,h+dh(s),w+dw(s)]
// s: 0=center, 1=(w+1), 2=(w-1), 3=(h+1), 4=(h-1)
// GEMM: C[pix, 192] = A[pix, 960] * B^T, A = shifted-gather of padded
// pixel-major fp16 x, B = W in native [o=192, k=960] (n-major) layout.
// ============================================================

#define BATCH 4
#define CCH   192
#define HDIM  256
#define WDIM  256
#define HP    258
#define WP    258
#define OCH   192
#define KTOT  (5 * CCH)   // 960

static constexpr int XPAD_ELEMS = BATCH * HP * WP * CCH;

__device__ __align__(16) __half g_xh[XPAD_ELEMS];
__device__ __align__(16) __half g_wh[OCH * KTOT];

// ---------------- helpers ----------------

__device__ __forceinline__ uint32_t smem_to_u32(const void* p) {
    uint32_t a;
    asm("{ .reg .u64 t; cvta.to.shared.u64 t, %1; cvt.u32.u64 %0, t; }"
        : "=r"(a) : "l"(p));
    return a;
}

__device__ __forceinline__ void cp_async16(uint32_t saddr, const void* gaddr) {
    asm volatile("cp.async.cg.shared.global [%0], [%1], 16;"
                 :: "r"(saddr), "l"(gaddr));
}
#define CP_COMMIT() asm volatile("cp.async.commit_group;" ::: "memory")
#define CP_WAIT2()  asm volatile("cp.async.wait_group 2;" ::: "memory")

__device__ __forceinline__ void ldsm4(uint32_t* r, uint32_t addr) {
    asm volatile("ldmatrix.sync.aligned.m8n8.x4.shared.b16 {%0,%1,%2,%3}, [%4];"
                 : "=r"(r[0]), "=r"(r[1]), "=r"(r[2]), "=r"(r[3]) : "r"(addr));
}

__device__ __forceinline__ void mma16816(float* c, const uint32_t* a,
                                         uint32_t b0, uint32_t b1) {
    asm volatile(
        "mma.sync.aligned.m16n8k16.row.col.f32.f16.f16.f32 "
        "{%0,%1,%2,%3}, {%4,%5,%6,%7}, {%8,%9}, {%0,%1,%2,%3};"
        : "+f"(c[0]), "+f"(c[1]), "+f"(c[2]), "+f"(c[3])
        : "r"(a[0]), "r"(a[1]), "r"(a[2]), "r"(a[3]), "r"(b0), "r"(b1));
}

// ---------------- prep kernels ----------------

// Zero the 1-pixel spatial border of the padded pixel-major array.
__global__ void prep_border() {
    const int per_b = 4 * WP * CCH;
    int i = blockIdx.x * blockDim.x + threadIdx.x;
    if (i >= BATCH * per_b) return;
    int b = i / per_b;
    int r = i % per_b;
    int line = r / (WP * CCH);
    int j = r % (WP * CCH);
    int pos = j / CCH;
    int c = j % CCH;
    int hh, ww;
    if      (line == 0) { hh = 0;      ww = pos; }
    else if (line == 1) { hh = HP - 1; ww = pos; }
    else if (line == 2) { hh = pos;    ww = 0;   }
    else                { hh = pos;    ww = WP - 1; }
    g_xh[(((size_t)b * HP + hh) * WP + ww) * CCH + c] = __float2half(0.0f);
}

// Transpose [B,C,H,W] fp32 -> padded pixel-major [B,HP,WP,C] fp16.
__global__ void prep_x(const float* __restrict__ x) {
    __shared__ float tile[32][33];
    int w0 = blockIdx.x * 32;
    int c0 = blockIdx.y * 32;
    int bh = blockIdx.z;
    int b = bh >> 8, h = bh & 255;
    int tx = threadIdx.x, ty = threadIdx.y;   // 32 x 8
#pragma unroll
    for (int i = 0; i < 4; i++) {
        int c = c0 + ty + i * 8;
        tile[ty + i * 8][tx] =
            x[(((size_t)b * CCH + c) * HDIM + h) * WDIM + (w0 + tx)];
    }
    __syncthreads();
#pragma unroll
    for (int i = 0; i < 4; i++) {
        int wl = ty + i * 8;
        float v = tile[tx][wl];
        size_t dst = (((size_t)b * HP + (h + 1)) * WP + (w0 + wl + 1)) * CCH
                     + c0 + tx;
        g_xh[dst] = __float2half(v);
    }
}

__global__ void prep_w(const float* __restrict__ W) {
    int i = blockIdx.x * blockDim.x + threadIdx.x;
    if (i >= OCH * KTOT) return;
    g_wh[i] = __float2half(W[i]);
}

// ---------------- main GEMM kernel ----------------
// CTA tile M=128 pixels x N=192 outputs, K=960, k-step 32, 4-stage cp.async.
// 256 threads, 8 warps in 2(M) x 4(N), warp tile 64x48.

static constexpr int STAGES   = 4;
static constexpr int A_ROWB   = 80;                 // 40 halfs (32 + 8 pad)
static constexpr int A_SZ     = 128 * A_ROWB;       // 10240 B / stage
static constexpr int B_SZ     = 192 * A_ROWB;       // 15360 B / stage
static constexpr int A_TOT    = STAGES * A_SZ;      // 40960
static constexpr int B_TOT    = STAGES * B_SZ;      // 61440
static constexpr int BIAS_OFF = A_TOT + B_TOT;      // 102400
static constexpr int SMEM_TOT = BIAS_OFF + OCH * 4; // 103168
static constexpr int KITERS   = 30;

__global__ __launch_bounds__(256, 1)
void shiftconv_gemm(const float* __restrict__ bias, float* __restrict__ out) {
    extern __shared__ char smem[];
    uint32_t sb = smem_to_u32(smem);
    float* bias_s = reinterpret_cast<float*>(smem + BIAS_OFF);

    int tid = threadIdx.x;
    int wid = tid >> 5;
    int lane = tid & 31;
    int wm = wid >> 2;         // 0..1  (M group of 64)
    int wn = wid & 3;          // 0..3  (N group of 48)

    // lane-derived ldmatrix decomposition
    int lm  = lane >> 3;       // matrix index 0..3
    int lr8 = lane & 7;        // row within 8
    int rowoff = (lm & 1) * 8 + lr8;
    int coloff = (lm >> 1) * 8;    // halfs

    int tile = blockIdx.x;                 // 0..2047
    int b  = tile >> 9;
    int h  = (tile >> 1) & 255;
    int w0 = (tile & 1) * 128;

    if (tid < OCH) bias_s[tid] = bias[tid];

    // A-fill role: thread handles row r, two 16B chunks
    int ar  = tid >> 1;                    // pixel row 0..127
    int ac0 = (tid & 1) * 2;               // chunk 0/2

    float acc[4][3][2][4];
#pragma unroll
    for (int mi = 0; mi < 4; mi++)
#pragma unroll
        for (int nj = 0; nj < 3; nj++)
#pragma unroll
            for (int hf = 0; hf < 2; hf++)
#pragma unroll
                for (int q = 0; q < 4; q++) acc[mi][nj][hf][q] = 0.0f;

    __syncthreads();   // bias_s visible; also before first cp.async use of smem

    // ---- issue lambda (stage s, k-iter it) ----
    auto issue = [&](int stage, int it) {
        int k0 = it * 32;
        int seg = k0 / CCH;
        int c0 = k0 - seg * CCH;
        int dh = (seg == 3) - (seg == 4);
        int dw = (seg == 1) - (seg == 2);
        // A: 128 rows x 64B
        {
            int hh = h + 1 + dh;
            int ww = w0 + ar + 1 + dw;
            const char* g = reinterpret_cast<const char*>(
                g_xh + (((size_t)b * HP + hh) * WP + ww) * CCH + c0);
            uint32_t s = sb + stage * A_SZ + ar * A_ROWB + ac0 * 16;
            cp_async16(s, g + ac0 * 16);
            cp_async16(s + 16, g + ac0 * 16 + 16);
        }
        // B: 192 rows x 64B  (768 chunks / 256 threads = 3 each)
        {
            uint32_t bbase = sb + A_TOT + stage * B_SZ;
            const char* gw = reinterpret_cast<const char*>(g_wh) + k0 * 2;
#pragma unroll
            for (int j = 0; j < 3; j++) {
                int id = tid + j * 256;
                int row = id >> 2;
                int ch = id & 3;
                cp_async16(bbase + row * A_ROWB + ch * 16,
                           gw + (size_t)row * (KTOT * 2) + ch * 16);
            }
        }
    };

    // prologue
#pragma unroll
    for (int s = 0; s < STAGES - 1; s++) { issue(s, s); CP_COMMIT(); }

    for (int it = 0; it < KITERS; ++it) {
        CP_WAIT2();
        __syncthreads();

        int stage = it & 3;
        uint32_t Ab = sb + stage * A_SZ;
        uint32_t Bb = sb + A_TOT + stage * B_SZ;

#pragma unroll
        for (int kk = 0; kk < 2; kk++) {
            uint32_t afr[4][4];
#pragma unroll
            for (int mi = 0; mi < 4; mi++) {
                int row = wm * 64 + mi * 16 + rowoff;
                int col = kk * 16 + coloff;
                ldsm4(afr[mi], Ab + row * A_ROWB + col * 2);
            }
            uint32_t bfr[3][4];
#pragma unroll
            for (int nj = 0; nj < 3; nj++) {
                int row = wn * 48 + nj * 16 + rowoff;
                int col = kk * 16 + coloff;
                ldsm4(bfr[nj], Bb + row * A_ROWB + col * 2);
            }
#pragma unroll
            for (int mi = 0; mi < 4; mi++)
#pragma unroll
                for (int nj = 0; nj < 3; nj++) {
                    mma16816(acc[mi][nj][0], afr[mi], bfr[nj][0], bfr[nj][2]);
                    mma16816(acc[mi][nj][1], afr[mi], bfr[nj][1], bfr[nj][3]);
                }
        }

        __syncthreads();   // all warps done reading stage before overwrite
        int nit = it + STAGES - 1;
        if (nit < KITERS) issue(nit & 3, nit);
        CP_COMMIT();
    }

    // ---- epilogue: direct STG (full 32B sectors: 8 pixels x 4B per o-row) ----
    int g8 = lane >> 2;       // 0..7 pixel sub-row
    int q  = lane & 3;        // o pair selector
    size_t out_hw = (size_t)h * WDIM + w0;
#pragma unroll
    for (int mi = 0; mi < 4; mi++) {
        int r0 = wm * 64 + mi * 16 + g8;
#pragma unroll
        for (int nj = 0; nj < 3; nj++)
#pragma unroll
            for (int hf = 0; hf < 2; hf++) {
                int o0 = wn * 48 + nj * 16 + hf * 8 + 2 * q;
                float bz0 = bias_s[o0];
                float bz1 = bias_s[o0 + 1];
                float* p0 = out + ((size_t)(b * OCH + o0)) * (HDIM * WDIM)
                            + out_hw;
                float* p1 = p0 + (size_t)(HDIM * WDIM);
                p0[r0]     = acc[mi][nj][hf][0] + bz0;
                p1[r0]     = acc[mi][nj][hf][1] + bz1;
                p0[r0 + 8] = acc[mi][nj][hf][2] + bz0;
                p1[r0 + 8] = acc[mi][nj][hf][3] + bz1;
            }
    }
}

// ---------------- launch ----------------

extern "C" void kernel_launch(void* const* d_in, const int* in_sizes, int n_in,
                              void* d_out, int out_size) {
    const float* x = (const float*)d_in[0];    // [4,192,256,256]
    const float* W = (const float*)d_in[1];    // [192, 960]
    const float* bias = (const float*)d_in[2]; // [192]
    float* out = (float*)d_out;

    {
        int n = BATCH * 4 * WP * CCH;
        prep_border<<<(n + 255) / 256, 256>>>();
    }
    prep_x<<<dim3(WDIM / 32, CCH / 32, BATCH * HDIM), dim3(32, 8)>>>(x);
    {
        int n = OCH * KTOT;
        prep_w<<<(n + 255) / 256, 256>>>(W);
    }
    cudaFuncSetAttribute(shiftconv_gemm,
                         cudaFuncAttributeMaxDynamicSharedMemorySize, SMEM_TOT);
    shiftconv_gemm<<<BATCH * HDIM * 2, 256, SMEM_TOT>>>(bias, out);
}

// round 3
// speedup vs baseline: 1.1317x; 1.1317x over previous
#include <cuda_runtime.h>
#include <cuda_fp16.h>
#include <cstdint>

// ============================================================
// ShiftConv (sm_103 non-'a' target): HMMA mma.sync fp16 GEMM.
// out[b,o,h,w] = bias[o] + sum_s sum_c W[o, s*192+c] * x[b,c,h+dh,w+dw]
// GEMM: C[pix, 192] = A[pix, 960] * W^T, A = shifted gather from padded
// pixel-major fp16 x.
// R3: CTA tile M64xN192, 2 CTAs/SM (occ 25%), 1 sync per k-iter,
// copies issued before MMA block for overlap.
// ============================================================

#define BATCH 4
#define CCH   192
#define HDIM  256
#define WDIM  256
#define HP    258
#define WP    258
#define OCH   192
#define KTOT  (5 * CCH)   // 960

static constexpr int XPAD_ELEMS = BATCH * HP * WP * CCH;

__device__ __align__(16) __half g_xh[XPAD_ELEMS];
__device__ __align__(16) __half g_wh[OCH * KTOT];

// ---------------- helpers ----------------

__device__ __forceinline__ uint32_t smem_to_u32(const void* p) {
    uint32_t a;
    asm("{ .reg .u64 t; cvta.to.shared.u64 t, %1; cvt.u32.u64 %0, t; }"
        : "=r"(a) : "l"(p));
    return a;
}

__device__ __forceinline__ void cp_async16(uint32_t saddr, const void* gaddr) {
    asm volatile("cp.async.cg.shared.global [%0], [%1], 16;"
                 :: "r"(saddr), "l"(gaddr));
}
#define CP_COMMIT() asm volatile("cp.async.commit_group;" ::: "memory")
#define CP_WAIT2()  asm volatile("cp.async.wait_group 2;" ::: "memory")

__device__ __forceinline__ void ldsm4(uint32_t* r, uint32_t addr) {
    asm volatile("ldmatrix.sync.aligned.m8n8.x4.shared.b16 {%0,%1,%2,%3}, [%4];"
                 : "=r"(r[0]), "=r"(r[1]), "=r"(r[2]), "=r"(r[3]) : "r"(addr));
}

__device__ __forceinline__ void mma16816(float* c, const uint32_t* a,
                                         uint32_t b0, uint32_t b1) {
    asm volatile(
        "mma.sync.aligned.m16n8k16.row.col.f32.f16.f16.f32 "
        "{%0,%1,%2,%3}, {%4,%5,%6,%7}, {%8,%9}, {%0,%1,%2,%3};"
        : "+f"(c[0]), "+f"(c[1]), "+f"(c[2]), "+f"(c[3])
        : "r"(a[0]), "r"(a[1]), "r"(a[2]), "r"(a[3]), "r"(b0), "r"(b1));
}

// ---------------- prep kernels ----------------

__global__ void prep_border() {
    const int per_b = 4 * WP * CCH;
    int i = blockIdx.x * blockDim.x + threadIdx.x;
    if (i >= BATCH * per_b) return;
    int b = i / per_b;
    int r = i % per_b;
    int line = r / (WP * CCH);
    int j = r % (WP * CCH);
    int pos = j / CCH;
    int c = j % CCH;
    int hh, ww;
    if      (line == 0) { hh = 0;      ww = pos; }
    else if (line == 1) { hh = HP - 1; ww = pos; }
    else if (line == 2) { hh = pos;    ww = 0;   }
    else                { hh = pos;    ww = WP - 1; }
    g_xh[(((size_t)b * HP + hh) * WP + ww) * CCH + c] = __float2half(0.0f);
}

__global__ void prep_x(const float* __restrict__ x) {
    __shared__ float tile[32][33];
    int w0 = blockIdx.x * 32;
    int c0 = blockIdx.y * 32;
    int bh = blockIdx.z;
    int b = bh >> 8, h = bh & 255;
    int tx = threadIdx.x, ty = threadIdx.y;   // 32 x 8
#pragma unroll
    for (int i = 0; i < 4; i++) {
        int c = c0 + ty + i * 8;
        tile[ty + i * 8][tx] =
            x[(((size_t)b * CCH + c) * HDIM + h) * WDIM + (w0 + tx)];
    }
    __syncthreads();
#pragma unroll
    for (int i = 0; i < 4; i++) {
        int wl = ty + i * 8;
        float v = tile[tx][wl];
        size_t dst = (((size_t)b * HP + (h + 1)) * WP + (w0 + wl + 1)) * CCH
                     + c0 + tx;
        g_xh[dst] = __float2half(v);
    }
}

__global__ void prep_w(const float* __restrict__ W) {
    int i = blockIdx.x * blockDim.x + threadIdx.x;
    if (i >= OCH * KTOT) return;
    g_wh[i] = __float2half(W[i]);
}

// ---------------- main GEMM kernel ----------------
// CTA tile M=64 pixels x N=192 outputs, K=960, k-step 32, 4-stage cp.async.
// 256 threads = 8 warps in 2(M) x 4(N); warp tile 32x48. 2 CTAs/SM.

static constexpr int STAGES   = 4;
static constexpr int A_ROWB   = 80;                 // 40 halfs (32 + 8 pad)
static constexpr int A_SZ     = 64 * A_ROWB;        // 5120 B / stage
static constexpr int B_SZ     = 192 * A_ROWB;       // 15360 B / stage
static constexpr int A_TOT    = STAGES * A_SZ;      // 20480
static constexpr int B_TOT    = STAGES * B_SZ;      // 61440
static constexpr int BIAS_OFF = A_TOT + B_TOT;      // 81920
static constexpr int SMEM_TOT = BIAS_OFF + OCH * 4; // 82688
static constexpr int KITERS   = 30;

__global__ __launch_bounds__(256, 2)
void shiftconv_gemm(const float* __restrict__ bias, float* __restrict__ out) {
    extern __shared__ char smem[];
    uint32_t sb = smem_to_u32(smem);
    float* bias_s = reinterpret_cast<float*>(smem + BIAS_OFF);

    int tid = threadIdx.x;
    int wid = tid >> 5;
    int lane = tid & 31;
    int wm = wid >> 2;         // 0..1  (M group of 32)
    int wn = wid & 3;          // 0..3  (N group of 48)

    int lm  = lane >> 3;       // ldmatrix matrix index 0..3
    int lr8 = lane & 7;
    int rowoff = (lm & 1) * 8 + lr8;
    int coloff = (lm >> 1) * 8;    // halfs

    int tile = blockIdx.x;                 // 0..4095
    int b  = tile >> 10;
    int h  = (tile >> 2) & 255;
    int w0 = (tile & 3) * 64;

    if (tid < OCH) bias_s[tid] = bias[tid];

    // A-fill: 64 rows x 4 x 16B chunks = 256 chunks -> 1 per thread
    int ar = tid >> 2;
    int ac = tid & 3;

    float acc[2][3][2][4];
#pragma unroll
    for (int mi = 0; mi < 2; mi++)
#pragma unroll
        for (int nj = 0; nj < 3; nj++)
#pragma unroll
            for (int hf = 0; hf < 2; hf++)
#pragma unroll
                for (int q = 0; q < 4; q++) acc[mi][nj][hf][q] = 0.0f;

    __syncthreads();

    auto issue = [&](int stage, int it) {
        int k0 = it * 32;
        int seg = k0 / CCH;
        int c0 = k0 - seg * CCH;
        int dh = (seg == 3) - (seg == 4);
        int dw = (seg == 1) - (seg == 2);
        {
            int hh = h + 1 + dh;
            int ww = w0 + ar + 1 + dw;
            const char* g = reinterpret_cast<const char*>(
                g_xh + (((size_t)b * HP + hh) * WP + ww) * CCH + c0);
            cp_async16(sb + stage * A_SZ + ar * A_ROWB + ac * 16, g + ac * 16);
        }
        {
            uint32_t bbase = sb + A_TOT + stage * B_SZ;
            const char* gw = reinterpret_cast<const char*>(g_wh) + k0 * 2;
#pragma unroll
            for (int j = 0; j < 3; j++) {
                int id = tid + j * 256;
                int row = id >> 2;
                int ch = id & 3;
                cp_async16(bbase + row * A_ROWB + ch * 16,
                           gw + (size_t)row * (KTOT * 2) + ch * 16);
            }
        }
    };

#pragma unroll
    for (int s = 0; s < STAGES - 1; s++) { issue(s, s); CP_COMMIT(); }

    for (int it = 0; it < KITERS; ++it) {
        CP_WAIT2();
        __syncthreads();   // stage it&3 ready; all warps done reading (it-1)&3

        int nit = it + STAGES - 1;
        if (nit < KITERS) issue(nit & 3, nit);
        CP_COMMIT();

        int stage = it & 3;
        uint32_t Ab = sb + stage * A_SZ;
        uint32_t Bb = sb + A_TOT + stage * B_SZ;

#pragma unroll
        for (int kk = 0; kk < 2; kk++) {
            uint32_t afr[2][4];
#pragma unroll
            for (int mi = 0; mi < 2; mi++) {
                int row = wm * 32 + mi * 16 + rowoff;
                int col = kk * 16 + coloff;
                ldsm4(afr[mi], Ab + row * A_ROWB + col * 2);
            }
            uint32_t bfr[3][4];
#pragma unroll
            for (int nj = 0; nj < 3; nj++) {
                int row = wn * 48 + nj * 16 + rowoff;
                int col = kk * 16 + coloff;
                ldsm4(bfr[nj], Bb + row * A_ROWB + col * 2);
            }
#pragma unroll
            for (int mi = 0; mi < 2; mi++)
#pragma unroll
                for (int nj = 0; nj < 3; nj++) {
                    mma16816(acc[mi][nj][0], afr[mi], bfr[nj][0], bfr[nj][2]);
                    mma16816(acc[mi][nj][1], afr[mi], bfr[nj][1], bfr[nj][3]);
                }
        }
    }

    // ---- epilogue: direct STG (8 consecutive pixels x 4B per store row) ----
    int g8 = lane >> 2;       // 0..7 pixel sub-row
    int q  = lane & 3;        // o pair selector
    size_t out_hw = (size_t)h * WDIM + w0;
#pragma unroll
    for (int mi = 0; mi < 2; mi++) {
        int r0 = wm * 32 + mi * 16 + g8;
#pragma unroll
        for (int nj = 0; nj < 3; nj++)
#pragma unroll
            for (int hf = 0; hf < 2; hf++) {
                int o0 = wn * 48 + nj * 16 + hf * 8 + 2 * q;
                float bz0 = bias_s[o0];
                float bz1 = bias_s[o0 + 1];
                float* p0 = out + ((size_t)(b * OCH + o0)) * (HDIM * WDIM)
                            + out_hw;
                float* p1 = p0 + (size_t)(HDIM * WDIM);
                p0[r0]     = acc[mi][nj][hf][0] + bz0;
                p1[r0]     = acc[mi][nj][hf][1] + bz1;
                p0[r0 + 8] = acc[mi][nj][hf][2] + bz0;
                p1[r0 + 8] = acc[mi][nj][hf][3] + bz1;
            }
    }
}

// ---------------- launch ----------------

extern "C" void kernel_launch(void* const* d_in, const int* in_sizes, int n_in,
                              void* d_out, int out_size) {
    const float* x = (const float*)d_in[0];    // [4,192,256,256]
    const float* W = (const float*)d_in[1];    // [192, 960]
    const float* bias = (const float*)d_in[2]; // [192]
    float* out = (float*)d_out;

    {
        int n = BATCH * 4 * WP * CCH;
        prep_border<<<(n + 255) / 256, 256>>>();
    }
    prep_x<<<dim3(WDIM / 32, CCH / 32, BATCH * HDIM), dim3(32, 8)>>>(x);
    {
        int n = OCH * KTOT;
        prep_w<<<(n + 255) / 256, 256>>>(W);
    }
    cudaFuncSetAttribute(shiftconv_gemm,
                         cudaFuncAttributeMaxDynamicSharedMemorySize, SMEM_TOT);
    shiftconv_gemm<<<BATCH * HDIM * 4, 256, SMEM_TOT>>>(bias, out);
}

// round 4
// speedup vs baseline: 1.1591x; 1.0242x over previous
#include <cuda_runtime.h>
#include <cuda_fp16.h>
#include <cstdint>

// ============================================================
// ShiftConv (sm_103 non-'a' target): HMMA mma.sync fp16 GEMM.
// out[b,o,h,w] = bias[o] + sum_s sum_c W[o, s*192+c] * x[b,c,h+dh,w+dw]
// GEMM: C[pix, 192] = A[pix, 960] * W^T, A = shifted gather from padded
// pixel-major fp16 x.
// R4: CTA tile M64xN96, 128 thr (4 warps 2x2, warp 32x48), 4 CTAs/SM,
// fully unrolled K loop with hoisted pointers (alu diet).
// ============================================================

#define BATCH 4
#define CCH   192
#define HDIM  256
#define WDIM  256
#define HP    258
#define WP    258
#define OCH   192
#define KTOT  (5 * CCH)   // 960

static constexpr int XPAD_ELEMS = BATCH * HP * WP * CCH;

__device__ __align__(16) __half g_xh[XPAD_ELEMS];
__device__ __align__(16) __half g_wh[OCH * KTOT];

// ---------------- helpers ----------------

__device__ __forceinline__ uint32_t smem_to_u32(const void* p) {
    uint32_t a;
    asm("{ .reg .u64 t; cvta.to.shared.u64 t, %1; cvt.u32.u64 %0, t; }"
        : "=r"(a) : "l"(p));
    return a;
}

__device__ __forceinline__ void cp_async16(uint32_t saddr, const void* gaddr) {
    asm volatile("cp.async.cg.shared.global [%0], [%1], 16;"
                 :: "r"(saddr), "l"(gaddr));
}
#define CP_COMMIT() asm volatile("cp.async.commit_group;" ::: "memory")
#define CP_WAIT2()  asm volatile("cp.async.wait_group 2;" ::: "memory")

__device__ __forceinline__ void ldsm4(uint32_t* r, uint32_t addr) {
    asm volatile("ldmatrix.sync.aligned.m8n8.x4.shared.b16 {%0,%1,%2,%3}, [%4];"
                 : "=r"(r[0]), "=r"(r[1]), "=r"(r[2]), "=r"(r[3]) : "r"(addr));
}

__device__ __forceinline__ void mma16816(float* c, const uint32_t* a,
                                         uint32_t b0, uint32_t b1) {
    asm volatile(
        "mma.sync.aligned.m16n8k16.row.col.f32.f16.f16.f32 "
        "{%0,%1,%2,%3}, {%4,%5,%6,%7}, {%8,%9}, {%0,%1,%2,%3};"
        : "+f"(c[0]), "+f"(c[1]), "+f"(c[2]), "+f"(c[3])
        : "r"(a[0]), "r"(a[1]), "r"(a[2]), "r"(a[3]), "r"(b0), "r"(b1));
}

// ---------------- prep kernels ----------------

__global__ void prep_border() {
    const int per_b = 4 * WP * CCH;
    int i = blockIdx.x * blockDim.x + threadIdx.x;
    if (i >= BATCH * per_b) return;
    int b = i / per_b;
    int r = i % per_b;
    int line = r / (WP * CCH);
    int j = r % (WP * CCH);
    int pos = j / CCH;
    int c = j % CCH;
    int hh, ww;
    if      (line == 0) { hh = 0;      ww = pos; }
    else if (line == 1) { hh = HP - 1; ww = pos; }
    else if (line == 2) { hh = pos;    ww = 0;   }
    else                { hh = pos;    ww = WP - 1; }
    g_xh[(((size_t)b * HP + hh) * WP + ww) * CCH + c] = __float2half(0.0f);
}

__global__ void prep_x(const float* __restrict__ x) {
    __shared__ float tile[32][33];
    int w0 = blockIdx.x * 32;
    int c0 = blockIdx.y * 32;
    int bh = blockIdx.z;
    int b = bh >> 8, h = bh & 255;
    int tx = threadIdx.x, ty = threadIdx.y;   // 32 x 8
#pragma unroll
    for (int i = 0; i < 4; i++) {
        int c = c0 + ty + i * 8;
        tile[ty + i * 8][tx] =
            x[(((size_t)b * CCH + c) * HDIM + h) * WDIM + (w0 + tx)];
    }
    __syncthreads();
#pragma unroll
    for (int i = 0; i < 4; i++) {
        int wl = ty + i * 8;
        float v = tile[tx][wl];
        size_t dst = (((size_t)b * HP + (h + 1)) * WP + (w0 + wl + 1)) * CCH
                     + c0 + tx;
        g_xh[dst] = __float2half(v);
    }
}

__global__ void prep_w(const float* __restrict__ W) {
    int i = blockIdx.x * blockDim.x + threadIdx.x;
    if (i >= OCH * KTOT) return;
    g_wh[i] = __float2half(W[i]);
}

// ---------------- main GEMM kernel ----------------
// CTA tile M=64 pixels x N=96 outputs, K=960, k-step 32, 4-stage cp.async.
// 128 threads = 4 warps in 2(M) x 2(N); warp tile 32x48. 4 CTAs/SM.

static constexpr int STAGES   = 4;
static constexpr int A_ROWB   = 80;                 // 40 halfs (32 + 8 pad)
static constexpr int A_SZ     = 64 * A_ROWB;        // 5120 B / stage
static constexpr int B_SZ     = 96 * A_ROWB;        // 7680 B / stage
static constexpr int A_TOT    = STAGES * A_SZ;      // 20480
static constexpr int SMEM_TOT = A_TOT + STAGES * B_SZ;  // 51200
static constexpr int KITERS   = 30;

__global__ __launch_bounds__(128, 4)
void shiftconv_gemm(const float* __restrict__ bias, float* __restrict__ out) {
    extern __shared__ char smem[];
    uint32_t sb = smem_to_u32(smem);

    int tid = threadIdx.x;
    int wid = tid >> 5;
    int lane = tid & 31;
    int wm = wid >> 1;         // 0..1  (M group of 32)
    int wn = wid & 1;          // 0..1  (N group of 48)

    int lm  = lane >> 3;       // ldmatrix matrix index 0..3
    int lr8 = lane & 7;
    int rowoff = (lm & 1) * 8 + lr8;
    int coloff = (lm >> 1) * 8;    // halfs

    int tile = blockIdx.x;                 // 0..8191
    int nh = tile & 1;                     // N half (o base 0 / 96)
    int w0 = ((tile >> 1) & 3) * 64;
    int h  = (tile >> 3) & 255;
    int b  = tile >> 11;
    int o0 = nh * 96;

    // ---- hoisted fill roles & pointers ----
    // A: 64 rows x 4 16B-chunks = 256 chunks, 128 threads -> 2 consecutive each
    int ar = tid >> 1;                     // pixel row 0..63
    int ac = (tid & 1) * 2;                // first chunk index (0 or 2)
    const __half* abase[5];
#pragma unroll
    for (int s = 0; s < 5; s++) {
        int dh = (s == 3) - (s == 4);
        int dw = (s == 1) - (s == 2);
        abase[s] = g_xh
            + (((size_t)b * HP + (h + 1 + dh)) * WP + (w0 + ar + 1 + dw)) * CCH
            + ac * 8;
    }
    uint32_t a_smem = sb + ar * A_ROWB + ac * 16;

    // B: 96 rows x 4 chunks = 384 chunks -> 3 per thread
    const __half* bptr[3];
    uint32_t b_smem[3];
#pragma unroll
    for (int j = 0; j < 3; j++) {
        int id = tid + j * 128;
        int row = id >> 2;
        int ch = id & 3;
        bptr[j] = g_wh + (size_t)(o0 + row) * KTOT + ch * 8;
        b_smem[j] = sb + A_TOT + row * A_ROWB + ch * 16;
    }

    float acc[2][3][2][4] = {};

    // ---- issue one k-chunk (all indices constant after full unroll) ----
    auto issue = [&](int it) {
        int stage = it & 3;
        int seg = it / 6;
        int c0 = (it - seg * 6) * 32;
        const char* ga = reinterpret_cast<const char*>(abase[seg] + c0);
        uint32_t sa = a_smem + stage * A_SZ;
        cp_async16(sa, ga);
        cp_async16(sa + 16, ga + 16);
#pragma unroll
        for (int j = 0; j < 3; j++) {
            cp_async16(b_smem[j] + stage * B_SZ,
                       reinterpret_cast<const char*>(bptr[j] + it * 32));
        }
    };

#pragma unroll
    for (int s = 0; s < STAGES - 1; s++) { issue(s); CP_COMMIT(); }

#pragma unroll
    for (int it = 0; it < KITERS; ++it) {
        CP_WAIT2();
        __syncthreads();   // stage it&3 ready; all warps done reading (it-1)&3

        if (it + STAGES - 1 < KITERS) issue(it + STAGES - 1);
        CP_COMMIT();

        int stage = it & 3;
        uint32_t Ab = sb + stage * A_SZ;
        uint32_t Bb = sb + A_TOT + stage * B_SZ;

#pragma unroll
        for (int kk = 0; kk < 2; kk++) {
            uint32_t afr[2][4];
#pragma unroll
            for (int mi = 0; mi < 2; mi++) {
                int row = wm * 32 + mi * 16 + rowoff;
                int col = kk * 16 + coloff;
                ldsm4(afr[mi], Ab + row * A_ROWB + col * 2);
            }
            uint32_t bfr[3][4];
#pragma unroll
            for (int nj = 0; nj < 3; nj++) {
                int row = wn * 48 + nj * 16 + rowoff;
                int col = kk * 16 + coloff;
                ldsm4(bfr[nj], Bb + row * A_ROWB + col * 2);
            }
#pragma unroll
            for (int mi = 0; mi < 2; mi++)
#pragma unroll
                for (int nj = 0; nj < 3; nj++) {
                    mma16816(acc[mi][nj][0], afr[mi], bfr[nj][0], bfr[nj][2]);
                    mma16816(acc[mi][nj][1], afr[mi], bfr[nj][1], bfr[nj][3]);
                }
        }
    }

    // ---- epilogue: direct STG (8 consecutive pixels x 4B per store row) ----
    int g8 = lane >> 2;       // 0..7 pixel sub-row
    int q  = lane & 3;        // o pair selector
    size_t out_hw = (size_t)h * WDIM + w0;
#pragma unroll
    for (int mi = 0; mi < 2; mi++) {
        int r0 = wm * 32 + mi * 16 + g8;
#pragma unroll
        for (int nj = 0; nj < 3; nj++)
#pragma unroll
            for (int hf = 0; hf < 2; hf++) {
                int o = o0 + wn * 48 + nj * 16 + hf * 8 + 2 * q;
                float bz0 = __ldg(bias + o);
                float bz1 = __ldg(bias + o + 1);
                float* p0 = out + ((size_t)(b * OCH + o)) * (HDIM * WDIM)
                            + out_hw;
                float* p1 = p0 + (size_t)(HDIM * WDIM);
                p0[r0]     = acc[mi][nj][hf][0] + bz0;
                p1[r0]     = acc[mi][nj][hf][1] + bz1;
                p0[r0 + 8] = acc[mi][nj][hf][2] + bz0;
                p1[r0 + 8] = acc[mi][nj][hf][3] + bz1;
            }
    }
}

// ---------------- launch ----------------

extern "C" void kernel_launch(void* const* d_in, const int* in_sizes, int n_in,
                              void* d_out, int out_size) {
    const float* x = (const float*)d_in[0];    // [4,192,256,256]
    const float* W = (const float*)d_in[1];    // [192, 960]
    const float* bias = (const float*)d_in[2]; // [192]
    float* out = (float*)d_out;

    {
        int n = BATCH * 4 * WP * CCH;
        prep_border<<<(n + 255) / 256, 256>>>();
    }
    prep_x<<<dim3(WDIM / 32, CCH / 32, BATCH * HDIM), dim3(32, 8)>>>(x);
    {
        int n = OCH * KTOT;
        prep_w<<<(n + 255) / 256, 256>>>(W);
    }
    cudaFuncSetAttribute(shiftconv_gemm,
                         cudaFuncAttributeMaxDynamicSharedMemorySize, SMEM_TOT);
    shiftconv_gemm<<<BATCH * HDIM * 4 * 2, 128, SMEM_TOT>>>(bias, out);
}

// round 5
// speedup vs baseline: 1.2617x; 1.0885x over previous
#include <cuda_runtime.h>
#include <cuda_fp16.h>
#include <cstdint>

// ============================================================
// ShiftConv (sm_103 non-'a' target): HMMA mma.sync fp16 GEMM.
// out[b,o,h,w] = bias[o] + sum_s sum_c W[o, s*192+c] * x[b,c,h+dh,w+dw]
// GEMM: C[pix, 192] = A[pix, 960] * W^T, A = shifted gather from padded
// pixel-major fp16 x.
// R5: B (weights) bypasses smem entirely — fragment-major packed W is
// loaded as 6x LDG.128 per warp-iter straight into mma register layout.
// A-only smem staging -> 20.5KB/CTA -> 5 CTAs/SM (20 warps).
// ============================================================

#define BATCH 4
#define CCH   192
#define HDIM  256
#define WDIM  256
#define HP    258
#define WP    258
#define OCH   192
#define KTOT  (5 * CCH)   // 960

static constexpr int XPAD_ELEMS = BATCH * HP * WP * CCH;

__device__ __align__(16) __half g_xh[XPAD_ELEMS];
// Fragment-major W: index = o*960 + it*32 + p*8 + j  (halfs)
//   it = k-chunk 0..29, p = lane%4, j = 8 halfs: [b0_kk0(2), b1_kk0(2),
//   b0_kk1(2), b1_kk1(2)] i.e. k = it*32 + {2p,2p+1, 2p+8,2p+9,
//   2p+16,2p+17, 2p+24,2p+25}
__device__ __align__(16) __half g_wf[OCH * KTOT];

// ---------------- helpers ----------------

__device__ __forceinline__ uint32_t smem_to_u32(const void* p) {
    uint32_t a;
    asm("{ .reg .u64 t; cvta.to.shared.u64 t, %1; cvt.u32.u64 %0, t; }"
        : "=r"(a) : "l"(p));
    return a;
}

__device__ __forceinline__ void cp_async16(uint32_t saddr, const void* gaddr) {
    asm volatile("cp.async.cg.shared.global [%0], [%1], 16;"
                 :: "r"(saddr), "l"(gaddr));
}
#define CP_COMMIT() asm volatile("cp.async.commit_group;" ::: "memory")
#define CP_WAIT2()  asm volatile("cp.async.wait_group 2;" ::: "memory")

__device__ __forceinline__ void ldsm4(uint32_t* r, uint32_t addr) {
    asm volatile("ldmatrix.sync.aligned.m8n8.x4.shared.b16 {%0,%1,%2,%3}, [%4];"
                 : "=r"(r[0]), "=r"(r[1]), "=r"(r[2]), "=r"(r[3]) : "r"(addr));
}

__device__ __forceinline__ void mma16816(float* c, const uint32_t* a,
                                         uint32_t b0, uint32_t b1) {
    asm volatile(
        "mma.sync.aligned.m16n8k16.row.col.f32.f16.f16.f32 "
        "{%0,%1,%2,%3}, {%4,%5,%6,%7}, {%8,%9}, {%0,%1,%2,%3};"
        : "+f"(c[0]), "+f"(c[1]), "+f"(c[2]), "+f"(c[3])
        : "r"(a[0]), "r"(a[1]), "r"(a[2]), "r"(a[3]), "r"(b0), "r"(b1));
}

// ---------------- prep kernels ----------------

__global__ void prep_border() {
    const int per_b = 4 * WP * CCH;
    int i = blockIdx.x * blockDim.x + threadIdx.x;
    if (i >= BATCH * per_b) return;
    int b = i / per_b;
    int r = i % per_b;
    int line = r / (WP * CCH);
    int j = r % (WP * CCH);
    int pos = j / CCH;
    int c = j % CCH;
    int hh, ww;
    if      (line == 0) { hh = 0;      ww = pos; }
    else if (line == 1) { hh = HP - 1; ww = pos; }
    else if (line == 2) { hh = pos;    ww = 0;   }
    else                { hh = pos;    ww = WP - 1; }
    g_xh[(((size_t)b * HP + hh) * WP + ww) * CCH + c] = __float2half(0.0f);
}

__global__ void prep_x(const float* __restrict__ x) {
    __shared__ float tile[32][33];
    int w0 = blockIdx.x * 32;
    int c0 = blockIdx.y * 32;
    int bh = blockIdx.z;
    int b = bh >> 8, h = bh & 255;
    int tx = threadIdx.x, ty = threadIdx.y;   // 32 x 8
#pragma unroll
    for (int i = 0; i < 4; i++) {
        int c = c0 + ty + i * 8;
        tile[ty + i * 8][tx] =
            x[(((size_t)b * CCH + c) * HDIM + h) * WDIM + (w0 + tx)];
    }
    __syncthreads();
#pragma unroll
    for (int i = 0; i < 4; i++) {
        int wl = ty + i * 8;
        float v = tile[tx][wl];
        size_t dst = (((size_t)b * HP + (h + 1)) * WP + (w0 + wl + 1)) * CCH
                     + c0 + tx;
        g_xh[dst] = __float2half(v);
    }
}

// Pack W fp32 [o,k] into fragment-major fp16 g_wf.
// One thread per (o, it, p): gathers 8 scattered k values, stores 16B.
__global__ void prep_w(const float* __restrict__ W) {
    int i = blockIdx.x * blockDim.x + threadIdx.x;   // 192*30*4 = 23040
    if (i >= OCH * 30 * 4) return;
    int p  = i & 3;
    int it = (i >> 2) % 30;
    int o  = i / 120;
    const float* src = W + (size_t)o * KTOT + it * 32 + p * 2;
    __half v[8];
#pragma unroll
    for (int q = 0; q < 4; q++) {            // q = k-octet: 0,8,16,24
        v[q * 2]     = __float2half(src[q * 8]);
        v[q * 2 + 1] = __float2half(src[q * 8 + 1]);
    }
    *reinterpret_cast<uint4*>(g_wf + (size_t)o * KTOT + it * 32 + p * 8) =
        *reinterpret_cast<uint4*>(v);
}

// ---------------- main GEMM kernel ----------------
// CTA tile M=64 pixels x N=96 outputs, K=960, k-step 32, 4-stage cp.async
// for A only. 128 threads = 4 warps 2(M)x2(N); warp tile 32x48. 5 CTAs/SM.
// B fragments: 6x LDG.128 per warp-iter from fragment-major g_wf.

static constexpr int STAGES   = 4;
static constexpr int A_ROWB   = 80;                 // 40 halfs (32 + 8 pad)
static constexpr int A_SZ     = 64 * A_ROWB;        // 5120 B / stage
static constexpr int SMEM_TOT = STAGES * A_SZ;      // 20480
static constexpr int KITERS   = 30;

__global__ __launch_bounds__(128, 5)
void shiftconv_gemm(const float* __restrict__ bias, float* __restrict__ out) {
    extern __shared__ char smem[];
    uint32_t sb = smem_to_u32(smem);

    int tid = threadIdx.x;
    int wid = tid >> 5;
    int lane = tid & 31;
    int wm = wid >> 1;         // 0..1  (M group of 32)
    int wn = wid & 1;          // 0..1  (N group of 48)

    int lm  = lane >> 3;       // ldmatrix matrix index 0..3
    int lr8 = lane & 7;
    int rowoff = (lm & 1) * 8 + lr8;
    int coloff = (lm >> 1) * 8;    // halfs

    int tile = blockIdx.x;                 // 0..8191
    int w0 = (tile & 3) * 64;
    int h  = (tile >> 2) & 255;
    int b  = (tile >> 10) & 3;
    int nh = tile >> 12;                   // N half SLOWEST -> W locality
    int o0 = nh * 96;

    // ---- A fill roles & hoisted pointers ----
    int ar = tid >> 1;                     // pixel row 0..63
    int ac = (tid & 1) * 2;                // first 16B chunk (0 or 2)
    const __half* abase[5];
#pragma unroll
    for (int s = 0; s < 5; s++) {
        int dh = (s == 3) - (s == 4);
        int dw = (s == 1) - (s == 2);
        abase[s] = g_xh
            + (((size_t)b * HP + (h + 1 + dh)) * WP + (w0 + ar + 1 + dw)) * CCH
            + ac * 8;
    }
    uint32_t a_smem = sb + ar * A_ROWB + ac * 16;

    // ---- B fragment base pointer (per lane) ----
    // o-row for (nj,hf) = o0 + wn*48 + nj*16 + hf*8 + lane/4
    const __half* wf0 = g_wf + (size_t)(o0 + wn * 48 + (lane >> 2)) * KTOT
                        + (lane & 3) * 8;

    float acc[2][3][2][4] = {};

    auto issueA = [&](int it) {
        int stage = it & 3;
        int seg = it / 6;
        int c0 = (it - seg * 6) * 32;
        const char* ga = reinterpret_cast<const char*>(abase[seg] + c0);
        uint32_t sa = a_smem + stage * A_SZ;
        cp_async16(sa, ga);
        cp_async16(sa + 16, ga + 16);
    };

#pragma unroll
    for (int s = 0; s < STAGES - 1; s++) { issueA(s); CP_COMMIT(); }

#pragma unroll
    for (int it = 0; it < KITERS; ++it) {
        // B fragments for this iter: 6 x LDG.128 (nj x hf), issued early.
        uint32_t bf[3][2][4];
#pragma unroll
        for (int nj = 0; nj < 3; nj++)
#pragma unroll
            for (int hf = 0; hf < 2; hf++) {
                const uint4* pB = reinterpret_cast<const uint4*>(
                    wf0 + (size_t)(nj * 16 + hf * 8) * KTOT + it * 32);
                uint4 v = __ldg(pB);
                bf[nj][hf][0] = v.x; bf[nj][hf][1] = v.y;
                bf[nj][hf][2] = v.z; bf[nj][hf][3] = v.w;
            }

        CP_WAIT2();
        __syncthreads();   // stage it&3 ready; all warps done reading (it-1)&3

        if (it + STAGES - 1 < KITERS) issueA(it + STAGES - 1);
        CP_COMMIT();

        uint32_t Ab = sb + (it & 3) * A_SZ;

#pragma unroll
        for (int kk = 0; kk < 2; kk++) {
            uint32_t afr[2][4];
#pragma unroll
            for (int mi = 0; mi < 2; mi++) {
                int row = wm * 32 + mi * 16 + rowoff;
                int col = kk * 16 + coloff;
                ldsm4(afr[mi], Ab + row * A_ROWB + col * 2);
            }
#pragma unroll
            for (int mi = 0; mi < 2; mi++)
#pragma unroll
                for (int nj = 0; nj < 3; nj++) {
                    mma16816(acc[mi][nj][0], afr[mi],
                             bf[nj][0][kk * 2], bf[nj][0][kk * 2 + 1]);
                    mma16816(acc[mi][nj][1], afr[mi],
                             bf[nj][1][kk * 2], bf[nj][1][kk * 2 + 1]);
                }
        }
    }

    // ---- epilogue: direct STG (8 consecutive pixels x 4B per store row) ----
    int g8 = lane >> 2;       // 0..7 pixel sub-row
    int q  = lane & 3;        // o pair selector
    size_t out_hw = (size_t)h * WDIM + w0;
#pragma unroll
    for (int mi = 0; mi < 2; mi++) {
        int r0 = wm * 32 + mi * 16 + g8;
#pragma unroll
        for (int nj = 0; nj < 3; nj++)
#pragma unroll
            for (int hf = 0; hf < 2; hf++) {
                int o = o0 + wn * 48 + nj * 16 + hf * 8 + 2 * q;
                float bz0 = __ldg(bias + o);
                float bz1 = __ldg(bias + o + 1);
                float* p0 = out + ((size_t)(b * OCH + o)) * (HDIM * WDIM)
                            + out_hw;
                float* p1 = p0 + (size_t)(HDIM * WDIM);
                p0[r0]     = acc[mi][nj][hf][0] + bz0;
                p1[r0]     = acc[mi][nj][hf][1] + bz1;
                p0[r0 + 8] = acc[mi][nj][hf][2] + bz0;
                p1[r0 + 8] = acc[mi][nj][hf][3] + bz1;
            }
    }
}

// ---------------- launch ----------------

extern "C" void kernel_launch(void* const* d_in, const int* in_sizes, int n_in,
                              void* d_out, int out_size) {
    const float* x = (const float*)d_in[0];    // [4,192,256,256]
    const float* W = (const float*)d_in[1];    // [192, 960]
    const float* bias = (const float*)d_in[2]; // [192]
    float* out = (float*)d_out;

    {
        int n = BATCH * 4 * WP * CCH;
        prep_border<<<(n + 255) / 256, 256>>>();
    }
    prep_x<<<dim3(WDIM / 32, CCH / 32, BATCH * HDIM), dim3(32, 8)>>>(x);
    {
        int n = OCH * 30 * 4;
        prep_w<<<(n + 255) / 256, 256>>>(W);
    }
    cudaFuncSetAttribute(shiftconv_gemm,
                         cudaFuncAttributeMaxDynamicSharedMemorySize, SMEM_TOT);
    shiftconv_gemm<<<BATCH * HDIM * 4 * 2, 128, SMEM_TOT>>>(bias, out);
}